// round 4
// baseline (speedup 1.0000x reference)
#include <cuda_runtime.h>
#include <cstdint>

#define NMAX   50000
#define EMAX   500000
#define ZDIM   136      // 16 (he) x 8 (x) + 8 (x bias lanes)
#define GRAPHS 64
#define EPS    1e-5f
#define SCAN_B 128
#define SCAN_T 512

typedef unsigned long long ull;

// packed fp32x2 helpers (Blackwell FFMA2)
#define DUP2(d, s)    asm("mov.b64 %0, {%1, %1};" : "=l"(d) : "f"(s))
#define FMA2(d, a, b) asm("fma.rn.f32x2 %0, %1, %2, %0;" : "+l"(d) : "l"(a), "l"(b))
#define PACK2(d, lo, hi) asm("mov.b64 %0, {%1, %2};" : "=l"(d) : "f"(lo), "f"(hi))
#define UNPACK2(lo, hi, s) asm("mov.b64 {%0, %1}, %2;" : "=f"(lo), "=f"(hi) : "l"(s))

// ---------------- scratch (device globals; zero-initialized at load) ----------------
__device__ int      g_cnt[NMAX];                    // degree histogram (left zeroed by k_scan)
__device__ int      g_off[NMAX + 1];                // CSR offsets
__device__ int      g_cur[NMAX];                    // scatter cursors
__device__ int      g_bsum[SCAN_B];                 // scan block totals+1 (left zeroed by k_scatter)
__device__ int      g_ssrc[EMAX];                   // dst-sorted src ids
__device__ float    g_she[(size_t)EMAX * 16];       // dst-sorted he vectors
__device__ float    g_pre[(size_t)NMAX * 64];       // NNConv pre-BN output
__device__ float    g_colsum[64];                   // (left zeroed by k_out)
__device__ float    g_colsq[64];
__device__ int      g_start[GRAPHS + 1];            // graph boundaries
__device__ float    g_gfeat[GRAPHS * 128];
__device__ float    g_y1[GRAPHS * 256];
__device__ float    g_y2[GRAPHS * 128];
__device__ float    g_y3[GRAPHS * 64];

// ---------------- histogram of dst + graph boundary scatter ----------------
__global__ void k_hist(const int* __restrict__ ei,
                       const int* __restrict__ batch,
                       int N, int E) {
    int i = blockIdx.x * blockDim.x + threadIdx.x;
    if (i < E) atomicAdd(&g_cnt[__ldg(&ei[E + i])], 1);
    if (i < N) {
        int bn = __ldg(&batch[i]);
        int bp = (i == 0) ? -1 : __ldg(&batch[i - 1]);
        for (int g = bp + 1; g <= bn; g++) g_start[g] = i;
        if (i == N - 1) {
            for (int g = bn + 1; g <= GRAPHS; g++) g_start[g] = N;
        }
    }
}

// ---------------- single-kernel scan (decoupled block totals; all blocks resident) ----------------
__global__ void k_scan(int N, int E) {
    __shared__ int sv[SCAN_T];
    __shared__ int sred[SCAN_T];
    int tid = threadIdx.x, b = blockIdx.x;
    int C = (N + SCAN_B - 1) / SCAN_B;
    int base0 = b * C, end = min(base0 + C, N);
    int run = 0;
    for (int t0 = base0; t0 < end; t0 += SCAN_T) {
        int idx = t0 + tid;
        int v = 0;
        if (idx < end) { v = g_cnt[idx]; g_cnt[idx] = 0; }   // read + reset for next replay
        sv[tid] = v;
        __syncthreads();
        for (int off = 1; off < SCAN_T; off <<= 1) {
            int u = (tid >= off) ? sv[tid - off] : 0;
            __syncthreads();
            sv[tid] += u;
            __syncthreads();
        }
        if (idx < end) g_off[idx] = run + sv[tid] - v;       // local exclusive
        run += sv[SCAN_T - 1];
        __syncthreads();
    }
    // publish this block's total (+1 so 0 == not ready)
    if (tid == 0) atomicExch(&g_bsum[b], run + 1);
    // gather totals of preceding blocks
    int v = 0;
    if (tid < b) {
        while ((v = atomicAdd(&g_bsum[tid], 0)) == 0) { }
        v -= 1;
    }
    sred[tid] = v;
    __syncthreads();
    for (int off = SCAN_T / 2; off > 0; off >>= 1) {
        if (tid < off) sred[tid] += sred[tid + off];
        __syncthreads();
    }
    int base = sred[0];
    for (int idx = base0 + tid; idx < end; idx += SCAN_T) {
        int o = g_off[idx] + base;
        g_off[idx] = o;
        g_cur[idx] = o;
    }
    if (b == SCAN_B - 1 && tid == 0) g_off[N] = E;
}

// ---------------- scatter: edge MLP (coalesced ea read) -> (he, src) at sorted pos ----------------
__global__ void k_scatter(const int* __restrict__ ei,
                          const float* __restrict__ ea,
                          const float* __restrict__ w_e1,
                          const float* __restrict__ b_e1,
                          int E) {
    __shared__ float sW1[128];
    __shared__ float sB1[16];
    if (threadIdx.x < 128) sW1[threadIdx.x] = w_e1[threadIdx.x];
    if (threadIdx.x < 16)  sB1[threadIdx.x] = b_e1[threadIdx.x];
    if (blockIdx.x == 0 && threadIdx.x < SCAN_B) g_bsum[threadIdx.x] = 0;  // reset for next replay
    __syncthreads();

    int e = blockIdx.x * blockDim.x + threadIdx.x;
    if (e >= E) return;

    int src = __ldg(&ei[e]);
    int dst = __ldg(&ei[E + e]);
    float4 a0 = __ldg((const float4*)(ea + (size_t)e * 8));
    float4 a1 = __ldg((const float4*)(ea + (size_t)e * 8 + 4));

    float he[16];
    #pragma unroll
    for (int j = 0; j < 16; j++) {
        float s = sB1[j];
        s = fmaf(a0.x, sW1[0 * 16 + j], s);
        s = fmaf(a0.y, sW1[1 * 16 + j], s);
        s = fmaf(a0.z, sW1[2 * 16 + j], s);
        s = fmaf(a0.w, sW1[3 * 16 + j], s);
        s = fmaf(a1.x, sW1[4 * 16 + j], s);
        s = fmaf(a1.y, sW1[5 * 16 + j], s);
        s = fmaf(a1.z, sW1[6 * 16 + j], s);
        s = fmaf(a1.w, sW1[7 * 16 + j], s);
        he[j] = fmaxf(s, 0.f);
    }

    int pos = atomicAdd(&g_cur[dst], 1);
    float4* hr = (float4*)(g_she + (size_t)pos * 16);
    hr[0] = make_float4(he[0], he[1], he[2], he[3]);
    hr[1] = make_float4(he[4], he[5], he[6], he[7]);
    hr[2] = make_float4(he[8], he[9], he[10], he[11]);
    hr[3] = make_float4(he[12], he[13], he[14], he[15]);
    g_ssrc[pos] = src;
}

// ---------------- fused: z-accumulate (CSR, no atomics) + node GEMM (f32x2) + BN stats ----------------
// block = 256 threads, 32 nodes. Phase 1: 8 threads/node, thread owns he pair {2*sub, 2*sub+1}.
// Phase 2: warp per 4 nodes, lane owns output-column pair {2*lane, 2*lane+1} via fma.rn.f32x2.
__global__ void k_fused(const float* __restrict__ x,
                        const float* __restrict__ w_e2,
                        const float* __restrict__ b_e2,
                        const float* __restrict__ root,
                        const float* __restrict__ cbias,
                        int N) {
    extern __shared__ char dynsmem[];
    ull*   sWc = (ull*)dynsmem;                          // [136][32] packed col pairs = 34816 B
    float* sZ  = (float*)(dynsmem + ZDIM * 32 * 8);      // [32][136] = 17408 B

    __shared__ float2 sRoot[8][32];
    __shared__ float  sCB[64];
    __shared__ float  sInvDeg[32];
    __shared__ float2 redS[8][32];
    __shared__ float2 redQ[8][32];

    int tid = threadIdx.x;

    // ---- load weights (packed) ----
    for (int idx = tid; idx < ZDIM * 32; idx += blockDim.x) {
        int k = idx >> 5, l = idx & 31;
        int h0 = 2 * l;
        float a, b;
        if (k < 128) {
            int j = k >> 3, f = k & 7;
            a = w_e2[j * 512 + f * 64 + h0];
            b = w_e2[j * 512 + f * 64 + h0 + 1];
        } else {
            int f = k - 128;
            a = b_e2[f * 64 + h0];
            b = b_e2[f * 64 + h0 + 1];
        }
        ull u; PACK2(u, a, b);
        sWc[k * 32 + l] = u;
    }
    for (int idx = tid; idx < 8 * 32; idx += blockDim.x) {
        int f = idx >> 5, l = idx & 31;
        sRoot[f][l] = make_float2(root[f * 64 + 2 * l], root[f * 64 + 2 * l + 1]);
    }
    if (tid < 64) sCB[tid] = cbias[tid];

    int nFirst = blockIdx.x * 32;

    // ---- phase 1: per-node z accumulation from CSR-sorted (he, src) ----
    {
        int gnode = tid >> 3;
        int sub   = tid & 7;
        int n = nFirst + gnode;
        int j0 = 2 * sub;
        int o0 = 0, o1 = 0;
        if (n < N) {
            o0 = __ldg(&g_off[n]);
            o1 = __ldg(&g_off[n + 1]);
        }

        float zacc[16];
        #pragma unroll
        for (int i = 0; i < 16; i++) zacc[i] = 0.f;
        float xs[8];
        #pragma unroll
        for (int i = 0; i < 8; i++) xs[i] = 0.f;

        for (int i = o0; i < o1; i++) {
            float2 h2 = __ldg((const float2*)(g_she + (size_t)i * 16 + j0));
            int src = __ldg(&g_ssrc[i]);
            const float4* xp = (const float4*)(x + (size_t)src * 8);
            float4 x0 = __ldg(xp);
            float4 x1 = __ldg(xp + 1);

            zacc[0] = fmaf(h2.x, x0.x, zacc[0]);
            zacc[1] = fmaf(h2.x, x0.y, zacc[1]);
            zacc[2] = fmaf(h2.x, x0.z, zacc[2]);
            zacc[3] = fmaf(h2.x, x0.w, zacc[3]);
            zacc[4] = fmaf(h2.x, x1.x, zacc[4]);
            zacc[5] = fmaf(h2.x, x1.y, zacc[5]);
            zacc[6] = fmaf(h2.x, x1.z, zacc[6]);
            zacc[7] = fmaf(h2.x, x1.w, zacc[7]);
            zacc[8]  = fmaf(h2.y, x0.x, zacc[8]);
            zacc[9]  = fmaf(h2.y, x0.y, zacc[9]);
            zacc[10] = fmaf(h2.y, x0.z, zacc[10]);
            zacc[11] = fmaf(h2.y, x0.w, zacc[11]);
            zacc[12] = fmaf(h2.y, x1.x, zacc[12]);
            zacc[13] = fmaf(h2.y, x1.y, zacc[13]);
            zacc[14] = fmaf(h2.y, x1.z, zacc[14]);
            zacc[15] = fmaf(h2.y, x1.w, zacc[15]);
            if (sub == 0) {
                xs[0] += x0.x; xs[1] += x0.y; xs[2] += x0.z; xs[3] += x0.w;
                xs[4] += x1.x; xs[5] += x1.y; xs[6] += x1.z; xs[7] += x1.w;
            }
        }

        float* zrow = sZ + gnode * ZDIM;
        #pragma unroll
        for (int f = 0; f < 8; f++) {
            zrow[j0 * 8 + f]       = zacc[f];
            zrow[(j0 + 1) * 8 + f] = zacc[8 + f];
        }
        if (sub == 0) {
            #pragma unroll
            for (int f = 0; f < 8; f++) zrow[128 + f] = xs[f];
            sInvDeg[gnode] = 1.f / fmaxf((float)(o1 - o0), 1.f);
        }
    }
    __syncthreads();

    // ---- phase 2: pre = (z @ Wc)*invdeg + x@root + bias (packed f32x2); BN stats ----
    int warp = tid >> 5, lane = tid & 31;
    int nlocbase = warp * 4;
    int nbase = nFirst + nlocbase;

    int  nn[4];
    bool valid[4];
    #pragma unroll
    for (int i = 0; i < 4; i++) {
        int nd = nbase + i;
        valid[i] = (nd < N);
        nn[i] = valid[i] ? nd : 0;
    }

    const float4* zr0 = (const float4*)(sZ + (nlocbase + 0) * ZDIM);
    const float4* zr1 = (const float4*)(sZ + (nlocbase + 1) * ZDIM);
    const float4* zr2 = (const float4*)(sZ + (nlocbase + 2) * ZDIM);
    const float4* zr3 = (const float4*)(sZ + (nlocbase + 3) * ZDIM);

    ull agg0 = 0ull, agg1 = 0ull, agg2 = 0ull, agg3 = 0ull;

    #pragma unroll 2
    for (int kk = 0; kk < ZDIM / 4; kk++) {
        float4 z0 = zr0[kk];
        float4 z1 = zr1[kk];
        float4 z2 = zr2[kk];
        float4 z3 = zr3[kk];
        ull wa = sWc[(4 * kk + 0) * 32 + lane];
        ull wb = sWc[(4 * kk + 1) * 32 + lane];
        ull wc = sWc[(4 * kk + 2) * 32 + lane];
        ull wd = sWc[(4 * kk + 3) * 32 + lane];
        ull t;
        DUP2(t, z0.x); FMA2(agg0, t, wa);
        DUP2(t, z0.y); FMA2(agg0, t, wb);
        DUP2(t, z0.z); FMA2(agg0, t, wc);
        DUP2(t, z0.w); FMA2(agg0, t, wd);
        DUP2(t, z1.x); FMA2(agg1, t, wa);
        DUP2(t, z1.y); FMA2(agg1, t, wb);
        DUP2(t, z1.z); FMA2(agg1, t, wc);
        DUP2(t, z1.w); FMA2(agg1, t, wd);
        DUP2(t, z2.x); FMA2(agg2, t, wa);
        DUP2(t, z2.y); FMA2(agg2, t, wb);
        DUP2(t, z2.z); FMA2(agg2, t, wc);
        DUP2(t, z2.w); FMA2(agg2, t, wd);
        DUP2(t, z3.x); FMA2(agg3, t, wa);
        DUP2(t, z3.y); FMA2(agg3, t, wb);
        DUP2(t, z3.z); FMA2(agg3, t, wc);
        DUP2(t, z3.w); FMA2(agg3, t, wd);
    }

    float aggx[4], aggy[4];
    UNPACK2(aggx[0], aggy[0], agg0);
    UNPACK2(aggx[1], aggy[1], agg1);
    UNPACK2(aggx[2], aggy[2], agg2);
    UNPACK2(aggx[3], aggy[3], agg3);

    float2 ls = make_float2(0.f, 0.f), lq = make_float2(0.f, 0.f);
    #pragma unroll
    for (int i = 0; i < 4; i++) {
        float2 p = make_float2(sCB[2 * lane], sCB[2 * lane + 1]);
        const float* xr = x + (size_t)nn[i] * 8;
        #pragma unroll
        for (int f = 0; f < 8; f++) {
            float xv = __ldg(xr + f);
            float2 rw = sRoot[f][lane];
            p.x = fmaf(xv, rw.x, p.x);
            p.y = fmaf(xv, rw.y, p.y);
        }
        float invd = sInvDeg[nlocbase + i];
        p.x = fmaf(aggx[i], invd, p.x);
        p.y = fmaf(aggy[i], invd, p.y);
        if (valid[i]) {
            g_pre[(size_t)nn[i] * 64 + 2 * lane]     = p.x;
            g_pre[(size_t)nn[i] * 64 + 2 * lane + 1] = p.y;
            ls.x += p.x; ls.y += p.y;
            lq.x = fmaf(p.x, p.x, lq.x);
            lq.y = fmaf(p.y, p.y, lq.y);
        }
    }
    redS[warp][lane] = ls;
    redQ[warp][lane] = lq;
    __syncthreads();
    if (tid < 32) {
        float2 S = make_float2(0.f, 0.f), Q = make_float2(0.f, 0.f);
        #pragma unroll
        for (int w = 0; w < 8; w++) {
            S.x += redS[w][tid].x; S.y += redS[w][tid].y;
            Q.x += redQ[w][tid].x; Q.y += redQ[w][tid].y;
        }
        atomicAdd(&g_colsum[2 * tid],     S.x);
        atomicAdd(&g_colsum[2 * tid + 1], S.y);
        atomicAdd(&g_colsq[2 * tid],      Q.x);
        atomicAdd(&g_colsq[2 * tid + 1],  Q.y);
    }
}

// ---------------- BN + relu + per-graph pool (one block per graph) ----------------
__global__ void k_pool(const float* __restrict__ gam,
                       const float* __restrict__ bet,
                       int N) {
    __shared__ float sScale[64], sShift[64];
    __shared__ float redS[8][64];
    __shared__ float redM[8][64];

    int tid = threadIdx.x;
    if (tid < 64) {
        float invN = 1.f / (float)N;
        float m = g_colsum[tid] * invN;
        float v = g_colsq[tid] * invN - m * m;
        float r = rsqrtf(v + EPS);
        float sc = r * __ldg(&gam[tid]);
        sScale[tid] = sc;
        sShift[tid] = __ldg(&bet[tid]) - m * sc;
    }
    __syncthreads();

    int rg = tid >> 6;
    int c  = tid & 63;
    int g = blockIdx.x;
    int s0 = g_start[g], s1 = g_start[g + 1];
    float sc = sScale[c], sh = sShift[c];

    float sum = 0.f, mx = 0.f;
    for (int n = s0 + rg; n < s1; n += 8) {
        float p = __ldg(&g_pre[(size_t)n * 64 + c]);
        float h = fmaxf(fmaf(p, sc, sh), 0.f);
        sum += h;
        mx = fmaxf(mx, h);
    }
    redS[rg][c] = sum;
    redM[rg][c] = mx;
    __syncthreads();
    if (tid < 64) {
        float S = 0.f, M = 0.f;
        #pragma unroll
        for (int r = 0; r < 8; r++) { S += redS[r][tid]; M = fmaxf(M, redM[r][tid]); }
        int cnt = s1 - s0;
        g_gfeat[g * 128 + tid]      = S / fmaxf((float)cnt, 1.f);
        g_gfeat[g * 128 + 64 + tid] = (cnt > 0) ? M : 0.f;
    }
}

// ---------------- fused linear + BN(over 64 rows) + relu ----------------
__global__ void k_layer(const float* __restrict__ in,   // [64, I]
                        const float* __restrict__ w,    // [I, O]
                        const float* __restrict__ b,
                        const float* __restrict__ gam,
                        const float* __restrict__ bet,
                        float* __restrict__ out,        // [64, O]
                        int I, int O) {
    extern __shared__ float sIn[];
    __shared__ float redS[8][32], redQ[8][32];
    __shared__ float sScale[32], sShift[32];

    int tid = threadIdx.x;
    for (int idx = tid; idx < 64 * I; idx += blockDim.x) sIn[idx] = in[idx];
    __syncthreads();

    int c = tid & 31, r0 = tid >> 5;
    int cg = blockIdx.x * 32 + c;

    float acc[8];
    float bv = __ldg(&b[cg]);
    #pragma unroll
    for (int i = 0; i < 8; i++) acc[i] = bv;

    for (int k = 0; k < I; k++) {
        float wv = __ldg(&w[k * O + cg]);
        #pragma unroll
        for (int i = 0; i < 8; i++)
            acc[i] = fmaf(sIn[(r0 + 8 * i) * I + k], wv, acc[i]);
    }

    float s = 0.f, q = 0.f;
    #pragma unroll
    for (int i = 0; i < 8; i++) { s += acc[i]; q = fmaf(acc[i], acc[i], q); }
    redS[r0][c] = s;
    redQ[r0][c] = q;
    __syncthreads();
    if (tid < 32) {
        float S = 0.f, Q = 0.f;
        #pragma unroll
        for (int w8 = 0; w8 < 8; w8++) { S += redS[w8][tid]; Q += redQ[w8][tid]; }
        float m = S * (1.f / 64.f);
        float v = Q * (1.f / 64.f) - m * m;
        float r = rsqrtf(v + EPS);
        float sc = r * __ldg(&gam[blockIdx.x * 32 + tid]);
        sScale[tid] = sc;
        sShift[tid] = __ldg(&bet[blockIdx.x * 32 + tid]) - m * sc;
    }
    __syncthreads();
    float sc = sScale[c], sh = sShift[c];
    #pragma unroll
    for (int i = 0; i < 8; i++)
        out[(r0 + 8 * i) * O + cg] = fmaxf(fmaf(acc[i], sc, sh), 0.f);
}

// ---------------- final projection [64,64]@[64,10] + scratch reset ----------------
__global__ void k_out(const float* __restrict__ wout,
                      const float* __restrict__ bout,
                      float* __restrict__ out) {
    int t = threadIdx.x;
    if (t < 64) { g_colsum[t] = 0.f; g_colsq[t] = 0.f; }   // reset for next replay
    if (t >= 640) return;
    int g = t / 10, o = t % 10;
    float s = __ldg(&bout[o]);
    #pragma unroll
    for (int k = 0; k < 64; k++)
        s = fmaf(g_y3[g * 64 + k], __ldg(&wout[k * 10 + o]), s);
    out[t] = s;
}

// ---------------- launch ----------------
extern "C" void kernel_launch(void* const* d_in, const int* in_sizes, int n_in,
                              void* d_out, int out_size) {
    const float* x      = (const float*)d_in[0];
    const int*   ei     = (const int*)  d_in[1];
    const float* ea     = (const float*)d_in[2];
    const int*   batch  = (const int*)  d_in[3];
    const float* w_e1   = (const float*)d_in[4];
    const float* b_e1   = (const float*)d_in[5];
    const float* w_e2   = (const float*)d_in[6];
    const float* b_e2   = (const float*)d_in[7];
    const float* root   = (const float*)d_in[8];
    const float* cbias  = (const float*)d_in[9];
    const float* g_bnc  = (const float*)d_in[10];
    const float* b_bnc  = (const float*)d_in[11];
    const float* w1     = (const float*)d_in[12];
    const float* b1     = (const float*)d_in[13];
    const float* g1     = (const float*)d_in[14];
    const float* be1    = (const float*)d_in[15];
    const float* w2     = (const float*)d_in[16];
    const float* b2     = (const float*)d_in[17];
    const float* g2     = (const float*)d_in[18];
    const float* be2    = (const float*)d_in[19];
    const float* w3     = (const float*)d_in[20];
    const float* b3     = (const float*)d_in[21];
    const float* g3     = (const float*)d_in[22];
    const float* be3    = (const float*)d_in[23];
    const float* wout   = (const float*)d_in[24];
    const float* bout   = (const float*)d_in[25];

    int N = in_sizes[0] / 8;
    int E = in_sizes[2] / 8;
    if (N > NMAX) N = NMAX;
    if (E > EMAX) E = EMAX;

    void *p_gfeat, *p_y1, *p_y2, *p_y3;
    cudaGetSymbolAddress(&p_gfeat, g_gfeat);
    cudaGetSymbolAddress(&p_y1, g_y1);
    cudaGetSymbolAddress(&p_y2, g_y2);
    cudaGetSymbolAddress(&p_y3, g_y3);

    const int fusedSmem = ZDIM * 32 * 8 + 32 * ZDIM * 4;   // sWc + sZ = 52224 B
    cudaFuncSetAttribute(k_fused, cudaFuncAttributeMaxDynamicSharedMemorySize, fusedSmem);
    cudaFuncSetAttribute(k_layer, cudaFuncAttributeMaxDynamicSharedMemorySize,
                         64 * 256 * (int)sizeof(float));

    int cover = (E > N ? E : N);
    k_hist<<<(cover + 255) / 256, 256>>>(ei, batch, N, E);
    k_scan<<<SCAN_B, SCAN_T>>>(N, E);
    k_scatter<<<(E + 255) / 256, 256>>>(ei, ea, w_e1, b_e1, E);
    k_fused<<<(N + 31) / 32, 256, fusedSmem>>>(x, w_e2, b_e2, root, cbias, N);
    k_pool<<<GRAPHS, 512>>>(g_bnc, b_bnc, N);
    k_layer<<<8, 256, 64 * 128 * sizeof(float)>>>((const float*)p_gfeat, w1, b1, g1, be1, (float*)p_y1, 128, 256);
    k_layer<<<4, 256, 64 * 256 * sizeof(float)>>>((const float*)p_y1,    w2, b2, g2, be2, (float*)p_y2, 256, 128);
    k_layer<<<2, 256, 64 * 128 * sizeof(float)>>>((const float*)p_y2,    w3, b3, g3, be3, (float*)p_y3, 128, 64);
    k_out<<<1, 640>>>(wout, bout, (float*)d_out);
}

// round 5
// speedup vs baseline: 1.0636x; 1.0636x over previous
#include <cuda_runtime.h>
#include <cstdint>

#define NMAX   50000
#define EMAX   500000
#define ZDIM   136      // 16 (he) x 8 (x) + 8 (x bias lanes)
#define GRAPHS 64
#define EPS    1e-5f
#define SCAN_B 128
#define SCAN_T 512

typedef unsigned long long ull;

// packed fp32x2 helpers (Blackwell FFMA2)
#define DUP2(d, s)    asm("mov.b64 %0, {%1, %1};" : "=l"(d) : "f"(s))
#define FMA2(d, a, b) asm("fma.rn.f32x2 %0, %1, %2, %0;" : "+l"(d) : "l"(a), "l"(b))
#define PACK2(d, lo, hi) asm("mov.b64 %0, {%1, %2};" : "=l"(d) : "f"(lo), "f"(hi))
#define UNPACK2(lo, hi, s) asm("mov.b64 {%0, %1}, %2;" : "=f"(lo), "=f"(hi) : "l"(s))

// ---------------- scratch (device globals; zero-initialized at load) ----------------
__device__ int      g_cnt[NMAX];                    // degree histogram (re-zeroed by k_scan)
__device__ int      g_off[NMAX + 1];                // CSR offsets
__device__ int      g_cur[NMAX];                    // scatter cursors
__device__ int      g_bsum[SCAN_B];                 // scan block totals+1 (re-zeroed by k_scatter)
__device__ int      g_ssrc[EMAX];                   // dst-sorted src ids
__device__ float    g_she[(size_t)EMAX * 16];       // dst-sorted he vectors
__device__ float    g_pre[(size_t)NMAX * 64];       // NNConv pre-BN output
__device__ float    g_colsum[64];                   // (re-zeroed by k_out)
__device__ float    g_colsq[64];
__device__ int      g_start[GRAPHS + 1];            // graph boundaries
__device__ float    g_gfeat[GRAPHS * 128];
__device__ float    g_y1[GRAPHS * 256];
__device__ float    g_y2[GRAPHS * 128];
__device__ float    g_y3[GRAPHS * 64];

// ---------------- histogram of dst + graph boundary scatter ----------------
__global__ void k_hist(const int* __restrict__ ei,
                       const int* __restrict__ batch,
                       int N, int E) {
    int i = blockIdx.x * blockDim.x + threadIdx.x;
    if (i < E) atomicAdd(&g_cnt[__ldg(&ei[E + i])], 1);
    if (i < N) {
        int bn = __ldg(&batch[i]);
        int bp = (i == 0) ? -1 : __ldg(&batch[i - 1]);
        for (int g = bp + 1; g <= bn; g++) g_start[g] = i;
        if (i == N - 1) {
            for (int g = bn + 1; g <= GRAPHS; g++) g_start[g] = N;
        }
    }
}

// ---------------- single-kernel scan (decoupled block totals; all blocks resident) ----------------
__global__ void k_scan(int N, int E) {
    __shared__ int sv[SCAN_T];
    __shared__ int sred[SCAN_T];
    int tid = threadIdx.x, b = blockIdx.x;
    int C = (N + SCAN_B - 1) / SCAN_B;
    int base0 = b * C, end = min(base0 + C, N);
    int run = 0;
    for (int t0 = base0; t0 < end; t0 += SCAN_T) {
        int idx = t0 + tid;
        int v = 0;
        if (idx < end) { v = g_cnt[idx]; g_cnt[idx] = 0; }   // read + reset for next replay
        sv[tid] = v;
        __syncthreads();
        for (int off = 1; off < SCAN_T; off <<= 1) {
            int u = (tid >= off) ? sv[tid - off] : 0;
            __syncthreads();
            sv[tid] += u;
            __syncthreads();
        }
        if (idx < end) g_off[idx] = run + sv[tid] - v;       // local exclusive
        run += sv[SCAN_T - 1];
        __syncthreads();
    }
    if (tid == 0) atomicExch(&g_bsum[b], run + 1);
    int v = 0;
    if (tid < b) {
        while ((v = atomicAdd(&g_bsum[tid], 0)) == 0) { }
        v -= 1;
    }
    sred[tid] = v;
    __syncthreads();
    for (int off = SCAN_T / 2; off > 0; off >>= 1) {
        if (tid < off) sred[tid] += sred[tid + off];
        __syncthreads();
    }
    int base = sred[0];
    for (int idx = base0 + tid; idx < end; idx += SCAN_T) {
        int o = g_off[idx] + base;
        g_off[idx] = o;
        g_cur[idx] = o;
    }
    if (b == SCAN_B - 1 && tid == 0) g_off[N] = E;
}

// ---------------- scatter: edge MLP (coalesced ea read) -> (he, src) at sorted pos ----------------
__global__ void k_scatter(const int* __restrict__ ei,
                          const float* __restrict__ ea,
                          const float* __restrict__ w_e1,
                          const float* __restrict__ b_e1,
                          int E) {
    __shared__ float sW1[128];
    __shared__ float sB1[16];
    if (threadIdx.x < 128) sW1[threadIdx.x] = w_e1[threadIdx.x];
    if (threadIdx.x < 16)  sB1[threadIdx.x] = b_e1[threadIdx.x];
    if (blockIdx.x == 0 && threadIdx.x < SCAN_B) g_bsum[threadIdx.x] = 0;  // reset for next replay
    __syncthreads();

    int e = blockIdx.x * blockDim.x + threadIdx.x;
    if (e >= E) return;

    int src = __ldg(&ei[e]);
    int dst = __ldg(&ei[E + e]);
    float4 a0 = __ldg((const float4*)(ea + (size_t)e * 8));
    float4 a1 = __ldg((const float4*)(ea + (size_t)e * 8 + 4));

    float he[16];
    #pragma unroll
    for (int j = 0; j < 16; j++) {
        float s = sB1[j];
        s = fmaf(a0.x, sW1[0 * 16 + j], s);
        s = fmaf(a0.y, sW1[1 * 16 + j], s);
        s = fmaf(a0.z, sW1[2 * 16 + j], s);
        s = fmaf(a0.w, sW1[3 * 16 + j], s);
        s = fmaf(a1.x, sW1[4 * 16 + j], s);
        s = fmaf(a1.y, sW1[5 * 16 + j], s);
        s = fmaf(a1.z, sW1[6 * 16 + j], s);
        s = fmaf(a1.w, sW1[7 * 16 + j], s);
        he[j] = fmaxf(s, 0.f);
    }

    int pos = atomicAdd(&g_cur[dst], 1);
    float4* hr = (float4*)(g_she + (size_t)pos * 16);
    hr[0] = make_float4(he[0], he[1], he[2], he[3]);
    hr[1] = make_float4(he[4], he[5], he[6], he[7]);
    hr[2] = make_float4(he[8], he[9], he[10], he[11]);
    hr[3] = make_float4(he[12], he[13], he[14], he[15]);
    g_ssrc[pos] = src;
}

// ---------------- fused: z-accumulate (CSR, no atomics) + node GEMM (f32x2) + BN stats ----------------
// block = 256 threads, 32 nodes. Phase 1: 8 threads/node, thread owns he pair {2*sub, 2*sub+1},
//   edge loop manually unrolled by 2 for MLP.
// Phase 2: warp per 4 nodes, lane owns output-column pair {2*lane, 2*lane+1} via fma.rn.f32x2.
__global__ void __launch_bounds__(256, 3)
k_fused(const float* __restrict__ x,
        const float* __restrict__ w_e2,
        const float* __restrict__ b_e2,
        const float* __restrict__ root,
        const float* __restrict__ cbias,
        int N) {
    extern __shared__ char dynsmem[];
    ull*   sWc = (ull*)dynsmem;                          // [136][32] packed col pairs = 34816 B
    float* sZ  = (float*)(dynsmem + ZDIM * 32 * 8);      // [32][136] = 17408 B
    // reduction buffers aliased onto sZ (used only after all z reads complete)
    float2* redS = (float2*)sZ;                          // [8][32] = 2048 B
    float2* redQ = (float2*)(sZ + 512);                  // [8][32] = 2048 B

    __shared__ float2 sRoot[8][32];
    __shared__ float  sCB[64];
    __shared__ float  sInvDeg[32];

    int tid = threadIdx.x;

    // ---- load weights (packed) ----
    for (int idx = tid; idx < ZDIM * 32; idx += blockDim.x) {
        int k = idx >> 5, l = idx & 31;
        int h0 = 2 * l;
        float a, b;
        if (k < 128) {
            int j = k >> 3, f = k & 7;
            a = w_e2[j * 512 + f * 64 + h0];
            b = w_e2[j * 512 + f * 64 + h0 + 1];
        } else {
            int f = k - 128;
            a = b_e2[f * 64 + h0];
            b = b_e2[f * 64 + h0 + 1];
        }
        ull u; PACK2(u, a, b);
        sWc[k * 32 + l] = u;
    }
    for (int idx = tid; idx < 8 * 32; idx += blockDim.x) {
        int f = idx >> 5, l = idx & 31;
        sRoot[f][l] = make_float2(root[f * 64 + 2 * l], root[f * 64 + 2 * l + 1]);
    }
    if (tid < 64) sCB[tid] = cbias[tid];

    int nFirst = blockIdx.x * 32;

    // ---- phase 1: per-node z accumulation from CSR-sorted (he, src), unroll 2 ----
    {
        int gnode = tid >> 3;
        int sub   = tid & 7;
        int n = nFirst + gnode;
        int j0 = 2 * sub;
        int o0 = 0, o1 = 0;
        if (n < N) {
            o0 = __ldg(&g_off[n]);
            o1 = __ldg(&g_off[n + 1]);
        }

        float zacc[16];
        #pragma unroll
        for (int i = 0; i < 16; i++) zacc[i] = 0.f;
        float xs[8];
        #pragma unroll
        for (int i = 0; i < 8; i++) xs[i] = 0.f;

        int i = o0;
        for (; i + 2 <= o1; i += 2) {
            // two independent load chains in flight
            float2 hA = __ldg((const float2*)(g_she + (size_t)i * 16 + j0));
            float2 hB = __ldg((const float2*)(g_she + (size_t)(i + 1) * 16 + j0));
            int sA = __ldg(&g_ssrc[i]);
            int sB = __ldg(&g_ssrc[i + 1]);
            const float4* xpA = (const float4*)(x + (size_t)sA * 8);
            const float4* xpB = (const float4*)(x + (size_t)sB * 8);
            float4 a0 = __ldg(xpA);
            float4 a1 = __ldg(xpA + 1);
            float4 b0 = __ldg(xpB);
            float4 b1 = __ldg(xpB + 1);

            zacc[0] = fmaf(hA.x, a0.x, zacc[0]);
            zacc[1] = fmaf(hA.x, a0.y, zacc[1]);
            zacc[2] = fmaf(hA.x, a0.z, zacc[2]);
            zacc[3] = fmaf(hA.x, a0.w, zacc[3]);
            zacc[4] = fmaf(hA.x, a1.x, zacc[4]);
            zacc[5] = fmaf(hA.x, a1.y, zacc[5]);
            zacc[6] = fmaf(hA.x, a1.z, zacc[6]);
            zacc[7] = fmaf(hA.x, a1.w, zacc[7]);
            zacc[8]  = fmaf(hA.y, a0.x, zacc[8]);
            zacc[9]  = fmaf(hA.y, a0.y, zacc[9]);
            zacc[10] = fmaf(hA.y, a0.z, zacc[10]);
            zacc[11] = fmaf(hA.y, a0.w, zacc[11]);
            zacc[12] = fmaf(hA.y, a1.x, zacc[12]);
            zacc[13] = fmaf(hA.y, a1.y, zacc[13]);
            zacc[14] = fmaf(hA.y, a1.z, zacc[14]);
            zacc[15] = fmaf(hA.y, a1.w, zacc[15]);

            zacc[0] = fmaf(hB.x, b0.x, zacc[0]);
            zacc[1] = fmaf(hB.x, b0.y, zacc[1]);
            zacc[2] = fmaf(hB.x, b0.z, zacc[2]);
            zacc[3] = fmaf(hB.x, b0.w, zacc[3]);
            zacc[4] = fmaf(hB.x, b1.x, zacc[4]);
            zacc[5] = fmaf(hB.x, b1.y, zacc[5]);
            zacc[6] = fmaf(hB.x, b1.z, zacc[6]);
            zacc[7] = fmaf(hB.x, b1.w, zacc[7]);
            zacc[8]  = fmaf(hB.y, b0.x, zacc[8]);
            zacc[9]  = fmaf(hB.y, b0.y, zacc[9]);
            zacc[10] = fmaf(hB.y, b0.z, zacc[10]);
            zacc[11] = fmaf(hB.y, b0.w, zacc[11]);
            zacc[12] = fmaf(hB.y, b1.x, zacc[12]);
            zacc[13] = fmaf(hB.y, b1.y, zacc[13]);
            zacc[14] = fmaf(hB.y, b1.z, zacc[14]);
            zacc[15] = fmaf(hB.y, b1.w, zacc[15]);

            if (sub == 0) {
                xs[0] += a0.x + b0.x; xs[1] += a0.y + b0.y;
                xs[2] += a0.z + b0.z; xs[3] += a0.w + b0.w;
                xs[4] += a1.x + b1.x; xs[5] += a1.y + b1.y;
                xs[6] += a1.z + b1.z; xs[7] += a1.w + b1.w;
            }
        }
        if (i < o1) {
            float2 h2 = __ldg((const float2*)(g_she + (size_t)i * 16 + j0));
            int src = __ldg(&g_ssrc[i]);
            const float4* xp = (const float4*)(x + (size_t)src * 8);
            float4 x0 = __ldg(xp);
            float4 x1 = __ldg(xp + 1);
            zacc[0] = fmaf(h2.x, x0.x, zacc[0]);
            zacc[1] = fmaf(h2.x, x0.y, zacc[1]);
            zacc[2] = fmaf(h2.x, x0.z, zacc[2]);
            zacc[3] = fmaf(h2.x, x0.w, zacc[3]);
            zacc[4] = fmaf(h2.x, x1.x, zacc[4]);
            zacc[5] = fmaf(h2.x, x1.y, zacc[5]);
            zacc[6] = fmaf(h2.x, x1.z, zacc[6]);
            zacc[7] = fmaf(h2.x, x1.w, zacc[7]);
            zacc[8]  = fmaf(h2.y, x0.x, zacc[8]);
            zacc[9]  = fmaf(h2.y, x0.y, zacc[9]);
            zacc[10] = fmaf(h2.y, x0.z, zacc[10]);
            zacc[11] = fmaf(h2.y, x0.w, zacc[11]);
            zacc[12] = fmaf(h2.y, x1.x, zacc[12]);
            zacc[13] = fmaf(h2.y, x1.y, zacc[13]);
            zacc[14] = fmaf(h2.y, x1.z, zacc[14]);
            zacc[15] = fmaf(h2.y, x1.w, zacc[15]);
            if (sub == 0) {
                xs[0] += x0.x; xs[1] += x0.y; xs[2] += x0.z; xs[3] += x0.w;
                xs[4] += x1.x; xs[5] += x1.y; xs[6] += x1.z; xs[7] += x1.w;
            }
        }

        float* zrow = sZ + gnode * ZDIM;
        #pragma unroll
        for (int f = 0; f < 8; f++) {
            zrow[j0 * 8 + f]       = zacc[f];
            zrow[(j0 + 1) * 8 + f] = zacc[8 + f];
        }
        if (sub == 0) {
            #pragma unroll
            for (int f = 0; f < 8; f++) zrow[128 + f] = xs[f];
            sInvDeg[gnode] = 1.f / fmaxf((float)(o1 - o0), 1.f);
        }
    }
    __syncthreads();

    // ---- phase 2: pre = (z @ Wc)*invdeg + x@root + bias (packed f32x2); BN stats ----
    int warp = tid >> 5, lane = tid & 31;
    int nlocbase = warp * 4;
    int nbase = nFirst + nlocbase;

    int  nn[4];
    bool valid[4];
    #pragma unroll
    for (int i = 0; i < 4; i++) {
        int nd = nbase + i;
        valid[i] = (nd < N);
        nn[i] = valid[i] ? nd : 0;
    }

    const float4* zr0 = (const float4*)(sZ + (nlocbase + 0) * ZDIM);
    const float4* zr1 = (const float4*)(sZ + (nlocbase + 1) * ZDIM);
    const float4* zr2 = (const float4*)(sZ + (nlocbase + 2) * ZDIM);
    const float4* zr3 = (const float4*)(sZ + (nlocbase + 3) * ZDIM);

    ull agg0 = 0ull, agg1 = 0ull, agg2 = 0ull, agg3 = 0ull;

    #pragma unroll 2
    for (int kk = 0; kk < ZDIM / 4; kk++) {
        float4 z0 = zr0[kk];
        float4 z1 = zr1[kk];
        float4 z2 = zr2[kk];
        float4 z3 = zr3[kk];
        ull wa = sWc[(4 * kk + 0) * 32 + lane];
        ull wb = sWc[(4 * kk + 1) * 32 + lane];
        ull wc = sWc[(4 * kk + 2) * 32 + lane];
        ull wd = sWc[(4 * kk + 3) * 32 + lane];
        ull t;
        DUP2(t, z0.x); FMA2(agg0, t, wa);
        DUP2(t, z0.y); FMA2(agg0, t, wb);
        DUP2(t, z0.z); FMA2(agg0, t, wc);
        DUP2(t, z0.w); FMA2(agg0, t, wd);
        DUP2(t, z1.x); FMA2(agg1, t, wa);
        DUP2(t, z1.y); FMA2(agg1, t, wb);
        DUP2(t, z1.z); FMA2(agg1, t, wc);
        DUP2(t, z1.w); FMA2(agg1, t, wd);
        DUP2(t, z2.x); FMA2(agg2, t, wa);
        DUP2(t, z2.y); FMA2(agg2, t, wb);
        DUP2(t, z2.z); FMA2(agg2, t, wc);
        DUP2(t, z2.w); FMA2(agg2, t, wd);
        DUP2(t, z3.x); FMA2(agg3, t, wa);
        DUP2(t, z3.y); FMA2(agg3, t, wb);
        DUP2(t, z3.z); FMA2(agg3, t, wc);
        DUP2(t, z3.w); FMA2(agg3, t, wd);
    }

    float aggx[4], aggy[4];
    UNPACK2(aggx[0], aggy[0], agg0);
    UNPACK2(aggx[1], aggy[1], agg1);
    UNPACK2(aggx[2], aggy[2], agg2);
    UNPACK2(aggx[3], aggy[3], agg3);

    float2 ls = make_float2(0.f, 0.f), lq = make_float2(0.f, 0.f);
    #pragma unroll
    for (int i = 0; i < 4; i++) {
        float2 p = make_float2(sCB[2 * lane], sCB[2 * lane + 1]);
        const float* xr = x + (size_t)nn[i] * 8;
        #pragma unroll
        for (int f = 0; f < 8; f++) {
            float xv = __ldg(xr + f);
            float2 rw = sRoot[f][lane];
            p.x = fmaf(xv, rw.x, p.x);
            p.y = fmaf(xv, rw.y, p.y);
        }
        float invd = sInvDeg[nlocbase + i];
        p.x = fmaf(aggx[i], invd, p.x);
        p.y = fmaf(aggy[i], invd, p.y);
        if (valid[i]) {
            g_pre[(size_t)nn[i] * 64 + 2 * lane]     = p.x;
            g_pre[(size_t)nn[i] * 64 + 2 * lane + 1] = p.y;
            ls.x += p.x; ls.y += p.y;
            lq.x = fmaf(p.x, p.x, lq.x);
            lq.y = fmaf(p.y, p.y, lq.y);
        }
    }
    // all z reads are done chip-wide in this block before aliasing sZ as reduction space
    __syncthreads();
    redS[warp * 32 + lane] = ls;
    redQ[warp * 32 + lane] = lq;
    __syncthreads();
    if (tid < 32) {
        float2 S = make_float2(0.f, 0.f), Q = make_float2(0.f, 0.f);
        #pragma unroll
        for (int w = 0; w < 8; w++) {
            S.x += redS[w * 32 + tid].x; S.y += redS[w * 32 + tid].y;
            Q.x += redQ[w * 32 + tid].x; Q.y += redQ[w * 32 + tid].y;
        }
        atomicAdd(&g_colsum[2 * tid],     S.x);
        atomicAdd(&g_colsum[2 * tid + 1], S.y);
        atomicAdd(&g_colsq[2 * tid],      Q.x);
        atomicAdd(&g_colsq[2 * tid + 1],  Q.y);
    }
}

// ---------------- BN + relu + per-graph pool (one block per graph) ----------------
__global__ void k_pool(const float* __restrict__ gam,
                       const float* __restrict__ bet,
                       int N) {
    __shared__ float sScale[64], sShift[64];
    __shared__ float redS[8][64];
    __shared__ float redM[8][64];

    int tid = threadIdx.x;
    if (tid < 64) {
        float invN = 1.f / (float)N;
        float m = g_colsum[tid] * invN;
        float v = g_colsq[tid] * invN - m * m;
        float r = rsqrtf(v + EPS);
        float sc = r * __ldg(&gam[tid]);
        sScale[tid] = sc;
        sShift[tid] = __ldg(&bet[tid]) - m * sc;
    }
    __syncthreads();

    int rg = tid >> 6;
    int c  = tid & 63;
    int g = blockIdx.x;
    int s0 = g_start[g], s1 = g_start[g + 1];
    float sc = sScale[c], sh = sShift[c];

    float sum = 0.f, mx = 0.f;
    for (int n = s0 + rg; n < s1; n += 8) {
        float p = __ldg(&g_pre[(size_t)n * 64 + c]);
        float h = fmaxf(fmaf(p, sc, sh), 0.f);
        sum += h;
        mx = fmaxf(mx, h);
    }
    redS[rg][c] = sum;
    redM[rg][c] = mx;
    __syncthreads();
    if (tid < 64) {
        float S = 0.f, M = 0.f;
        #pragma unroll
        for (int r = 0; r < 8; r++) { S += redS[r][tid]; M = fmaxf(M, redM[r][tid]); }
        int cnt = s1 - s0;
        g_gfeat[g * 128 + tid]      = S / fmaxf((float)cnt, 1.f);
        g_gfeat[g * 128 + 64 + tid] = (cnt > 0) ? M : 0.f;
    }
}

// ---------------- fused linear + BN(over 64 rows) + relu ----------------
__global__ void k_layer(const float* __restrict__ in,   // [64, I]
                        const float* __restrict__ w,    // [I, O]
                        const float* __restrict__ b,
                        const float* __restrict__ gam,
                        const float* __restrict__ bet,
                        float* __restrict__ out,        // [64, O]
                        int I, int O) {
    extern __shared__ float sIn[];
    __shared__ float redS[8][32], redQ[8][32];
    __shared__ float sScale[32], sShift[32];

    int tid = threadIdx.x;
    for (int idx = tid; idx < 64 * I; idx += blockDim.x) sIn[idx] = in[idx];
    __syncthreads();

    int c = tid & 31, r0 = tid >> 5;
    int cg = blockIdx.x * 32 + c;

    float acc[8];
    float bv = __ldg(&b[cg]);
    #pragma unroll
    for (int i = 0; i < 8; i++) acc[i] = bv;

    for (int k = 0; k < I; k++) {
        float wv = __ldg(&w[k * O + cg]);
        #pragma unroll
        for (int i = 0; i < 8; i++)
            acc[i] = fmaf(sIn[(r0 + 8 * i) * I + k], wv, acc[i]);
    }

    float s = 0.f, q = 0.f;
    #pragma unroll
    for (int i = 0; i < 8; i++) { s += acc[i]; q = fmaf(acc[i], acc[i], q); }
    redS[r0][c] = s;
    redQ[r0][c] = q;
    __syncthreads();
    if (tid < 32) {
        float S = 0.f, Q = 0.f;
        #pragma unroll
        for (int w8 = 0; w8 < 8; w8++) { S += redS[w8][tid]; Q += redQ[w8][tid]; }
        float m = S * (1.f / 64.f);
        float v = Q * (1.f / 64.f) - m * m;
        float r = rsqrtf(v + EPS);
        float sc = r * __ldg(&gam[blockIdx.x * 32 + tid]);
        sScale[tid] = sc;
        sShift[tid] = __ldg(&bet[blockIdx.x * 32 + tid]) - m * sc;
    }
    __syncthreads();
    float sc = sScale[c], sh = sShift[c];
    #pragma unroll
    for (int i = 0; i < 8; i++)
        out[(r0 + 8 * i) * O + cg] = fmaxf(fmaf(acc[i], sc, sh), 0.f);
}

// ---------------- final projection [64,64]@[64,10] + scratch reset ----------------
__global__ void k_out(const float* __restrict__ wout,
                      const float* __restrict__ bout,
                      float* __restrict__ out) {
    int t = threadIdx.x;
    if (t < 64) { g_colsum[t] = 0.f; g_colsq[t] = 0.f; }   // reset for next replay
    if (t >= 640) return;
    int g = t / 10, o = t % 10;
    float s = __ldg(&bout[o]);
    #pragma unroll
    for (int k = 0; k < 64; k++)
        s = fmaf(g_y3[g * 64 + k], __ldg(&wout[k * 10 + o]), s);
    out[t] = s;
}

// ---------------- launch ----------------
extern "C" void kernel_launch(void* const* d_in, const int* in_sizes, int n_in,
                              void* d_out, int out_size) {
    const float* x      = (const float*)d_in[0];
    const int*   ei     = (const int*)  d_in[1];
    const float* ea     = (const float*)d_in[2];
    const int*   batch  = (const int*)  d_in[3];
    const float* w_e1   = (const float*)d_in[4];
    const float* b_e1   = (const float*)d_in[5];
    const float* w_e2   = (const float*)d_in[6];
    const float* b_e2   = (const float*)d_in[7];
    const float* root   = (const float*)d_in[8];
    const float* cbias  = (const float*)d_in[9];
    const float* g_bnc  = (const float*)d_in[10];
    const float* b_bnc  = (const float*)d_in[11];
    const float* w1     = (const float*)d_in[12];
    const float* b1     = (const float*)d_in[13];
    const float* g1     = (const float*)d_in[14];
    const float* be1    = (const float*)d_in[15];
    const float* w2     = (const float*)d_in[16];
    const float* b2     = (const float*)d_in[17];
    const float* g2     = (const float*)d_in[18];
    const float* be2    = (const float*)d_in[19];
    const float* w3     = (const float*)d_in[20];
    const float* b3     = (const float*)d_in[21];
    const float* g3     = (const float*)d_in[22];
    const float* be3    = (const float*)d_in[23];
    const float* wout   = (const float*)d_in[24];
    const float* bout   = (const float*)d_in[25];

    int N = in_sizes[0] / 8;
    int E = in_sizes[2] / 8;
    if (N > NMAX) N = NMAX;
    if (E > EMAX) E = EMAX;

    void *p_gfeat, *p_y1, *p_y2, *p_y3;
    cudaGetSymbolAddress(&p_gfeat, g_gfeat);
    cudaGetSymbolAddress(&p_y1, g_y1);
    cudaGetSymbolAddress(&p_y2, g_y2);
    cudaGetSymbolAddress(&p_y3, g_y3);

    const int fusedSmem = ZDIM * 32 * 8 + 32 * ZDIM * 4;   // sWc + sZ = 52224 B
    cudaFuncSetAttribute(k_fused, cudaFuncAttributeMaxDynamicSharedMemorySize, fusedSmem);
    cudaFuncSetAttribute(k_layer, cudaFuncAttributeMaxDynamicSharedMemorySize,
                         64 * 256 * (int)sizeof(float));

    int cover = (E > N ? E : N);
    k_hist<<<(cover + 255) / 256, 256>>>(ei, batch, N, E);
    k_scan<<<SCAN_B, SCAN_T>>>(N, E);
    k_scatter<<<(E + 255) / 256, 256>>>(ei, ea, w_e1, b_e1, E);
    k_fused<<<(N + 31) / 32, 256, fusedSmem>>>(x, w_e2, b_e2, root, cbias, N);
    k_pool<<<GRAPHS, 512>>>(g_bnc, b_bnc, N);
    k_layer<<<8, 256, 64 * 128 * sizeof(float)>>>((const float*)p_gfeat, w1, b1, g1, be1, (float*)p_y1, 128, 256);
    k_layer<<<4, 256, 64 * 256 * sizeof(float)>>>((const float*)p_y1,    w2, b2, g2, be2, (float*)p_y2, 256, 128);
    k_layer<<<2, 256, 64 * 128 * sizeof(float)>>>((const float*)p_y2,    w3, b3, g3, be3, (float*)p_y3, 128, 64);
    k_out<<<1, 640>>>(wout, bout, (float*)d_out);
}

// round 6
// speedup vs baseline: 1.1213x; 1.0542x over previous
#include <cuda_runtime.h>
#include <cstdint>

#define NMAX   50000
#define EMAX   500000
#define ZDIM   136      // 16 (he) x 8 (x) + 8 (x bias lanes)
#define GRAPHS 64
#define EPS    1e-5f
#define SCAN_B 128
#define SCAN_T 512

typedef unsigned long long ull;

// packed fp32x2 helpers (Blackwell FFMA2)
#define DUP2(d, s)    asm("mov.b64 %0, {%1, %1};" : "=l"(d) : "f"(s))
#define FMA2(d, a, b) asm("fma.rn.f32x2 %0, %1, %2, %0;" : "+l"(d) : "l"(a), "l"(b))
#define PACK2(d, lo, hi) asm("mov.b64 %0, {%1, %2};" : "=l"(d) : "f"(lo), "f"(hi))
#define UNPACK2(lo, hi, s) asm("mov.b64 {%0, %1}, %2;" : "=f"(lo), "=f"(hi) : "l"(s))

// ---------------- scratch (device globals; zero-initialized at load) ----------------
__device__ int      g_cnt[NMAX];                    // degree histogram (re-zeroed by k_scan)
__device__ int      g_off[NMAX + 1];                // CSR offsets
__device__ int      g_cur[NMAX];                    // scatter cursors
__device__ int      g_bsum[SCAN_B];                 // scan block totals+1 (re-zeroed by k_scatter)
__device__ int      g_ssrc[EMAX];                   // dst-sorted src ids
__device__ float    g_she[(size_t)EMAX * 16];       // dst-sorted he vectors
__device__ float    g_pre[(size_t)NMAX * 64];       // NNConv pre-BN output
__device__ float    g_colsum[64];                   // (re-zeroed by k_out)
__device__ float    g_colsq[64];
__device__ int      g_start[GRAPHS + 1];            // graph boundaries
__device__ float    g_gfeat[GRAPHS * 128];
__device__ float    g_y1[GRAPHS * 256];
__device__ float    g_y2[GRAPHS * 128];
__device__ float    g_y3[GRAPHS * 64];

// ---------------- histogram of dst + graph boundary scatter ----------------
__global__ void k_hist(const int* __restrict__ ei,
                       const int* __restrict__ batch,
                       int N, int E) {
    int i = blockIdx.x * blockDim.x + threadIdx.x;
    if (i < E) atomicAdd(&g_cnt[__ldg(&ei[E + i])], 1);
    if (i < N) {
        int bn = __ldg(&batch[i]);
        int bp = (i == 0) ? -1 : __ldg(&batch[i - 1]);
        for (int g = bp + 1; g <= bn; g++) g_start[g] = i;
        if (i == N - 1) {
            for (int g = bn + 1; g <= GRAPHS; g++) g_start[g] = N;
        }
    }
}

// ---------------- single-kernel scan (decoupled block totals; all blocks resident) ----------------
__global__ void k_scan(int N, int E) {
    __shared__ int sv[SCAN_T];
    __shared__ int sred[SCAN_T];
    int tid = threadIdx.x, b = blockIdx.x;
    int C = (N + SCAN_B - 1) / SCAN_B;
    int base0 = b * C, end = min(base0 + C, N);
    int run = 0;
    for (int t0 = base0; t0 < end; t0 += SCAN_T) {
        int idx = t0 + tid;
        int v = 0;
        if (idx < end) { v = g_cnt[idx]; g_cnt[idx] = 0; }   // read + reset for next replay
        sv[tid] = v;
        __syncthreads();
        for (int off = 1; off < SCAN_T; off <<= 1) {
            int u = (tid >= off) ? sv[tid - off] : 0;
            __syncthreads();
            sv[tid] += u;
            __syncthreads();
        }
        if (idx < end) g_off[idx] = run + sv[tid] - v;       // local exclusive
        run += sv[SCAN_T - 1];
        __syncthreads();
    }
    if (tid == 0) atomicExch(&g_bsum[b], run + 1);
    int v = 0;
    if (tid < b) {
        while ((v = atomicAdd(&g_bsum[tid], 0)) == 0) { }
        v -= 1;
    }
    sred[tid] = v;
    __syncthreads();
    for (int off = SCAN_T / 2; off > 0; off >>= 1) {
        if (tid < off) sred[tid] += sred[tid + off];
        __syncthreads();
    }
    int base = sred[0];
    for (int idx = base0 + tid; idx < end; idx += SCAN_T) {
        int o = g_off[idx] + base;
        g_off[idx] = o;
        g_cur[idx] = o;
    }
    if (b == SCAN_B - 1 && tid == 0) g_off[N] = E;
}

// ---------------- scatter: edge MLP (coalesced ea read) -> (he, src) at sorted pos ----------------
__global__ void k_scatter(const int* __restrict__ ei,
                          const float* __restrict__ ea,
                          const float* __restrict__ w_e1,
                          const float* __restrict__ b_e1,
                          int E) {
    __shared__ float sW1[128];
    __shared__ float sB1[16];
    if (threadIdx.x < 128) sW1[threadIdx.x] = w_e1[threadIdx.x];
    if (threadIdx.x < 16)  sB1[threadIdx.x] = b_e1[threadIdx.x];
    if (blockIdx.x == 0 && threadIdx.x < SCAN_B) g_bsum[threadIdx.x] = 0;  // reset for next replay
    __syncthreads();

    int e = blockIdx.x * blockDim.x + threadIdx.x;
    if (e >= E) return;

    int src = __ldg(&ei[e]);
    int dst = __ldg(&ei[E + e]);
    float4 a0 = __ldg((const float4*)(ea + (size_t)e * 8));
    float4 a1 = __ldg((const float4*)(ea + (size_t)e * 8 + 4));

    float he[16];
    #pragma unroll
    for (int j = 0; j < 16; j++) {
        float s = sB1[j];
        s = fmaf(a0.x, sW1[0 * 16 + j], s);
        s = fmaf(a0.y, sW1[1 * 16 + j], s);
        s = fmaf(a0.z, sW1[2 * 16 + j], s);
        s = fmaf(a0.w, sW1[3 * 16 + j], s);
        s = fmaf(a1.x, sW1[4 * 16 + j], s);
        s = fmaf(a1.y, sW1[5 * 16 + j], s);
        s = fmaf(a1.z, sW1[6 * 16 + j], s);
        s = fmaf(a1.w, sW1[7 * 16 + j], s);
        he[j] = fmaxf(s, 0.f);
    }

    int pos = atomicAdd(&g_cur[dst], 1);
    float4* hr = (float4*)(g_she + (size_t)pos * 16);
    hr[0] = make_float4(he[0], he[1], he[2], he[3]);
    hr[1] = make_float4(he[4], he[5], he[6], he[7]);
    hr[2] = make_float4(he[8], he[9], he[10], he[11]);
    hr[3] = make_float4(he[12], he[13], he[14], he[15]);
    g_ssrc[pos] = src;
}

// ---------------- fused: z-accumulate (CSR, no atomics) + node GEMM (f32x2) + BN stats ----------------
// block = 256 threads, 64 nodes. Phase 1 (x2 halves): 8 threads/node, thread owns he pair.
// Phase 2: warp per 8 nodes, lane owns output-column pair {2*lane, 2*lane+1} via fma.rn.f32x2;
//   weight smem loads amortized over 8 nodes (2x reuse vs previous version).
__global__ void __launch_bounds__(256, 3)
k_fused(const float* __restrict__ x,
        const float* __restrict__ w_e2,
        const float* __restrict__ b_e2,
        const float* __restrict__ root,
        const float* __restrict__ cbias,
        int N) {
    extern __shared__ char dynsmem[];
    ull*   sWc = (ull*)dynsmem;                          // [136][32] packed col pairs = 34816 B
    float* sZ  = (float*)(dynsmem + ZDIM * 32 * 8);      // [64][136] = 34816 B
    // reduction buffers aliased onto sZ (used only after all z reads complete)
    float2* redS = (float2*)sZ;                          // [8][32] = 2048 B
    float2* redQ = (float2*)(sZ + 512);                  // [8][32] = 2048 B

    __shared__ float2 sRoot[8][32];
    __shared__ float  sCB[64];
    __shared__ float  sInvDeg[64];

    int tid = threadIdx.x;

    // ---- load weights (packed) ----
    for (int idx = tid; idx < ZDIM * 32; idx += blockDim.x) {
        int k = idx >> 5, l = idx & 31;
        int h0 = 2 * l;
        float a, b;
        if (k < 128) {
            int j = k >> 3, f = k & 7;
            a = w_e2[j * 512 + f * 64 + h0];
            b = w_e2[j * 512 + f * 64 + h0 + 1];
        } else {
            int f = k - 128;
            a = b_e2[f * 64 + h0];
            b = b_e2[f * 64 + h0 + 1];
        }
        ull u; PACK2(u, a, b);
        sWc[k * 32 + l] = u;
    }
    for (int idx = tid; idx < 8 * 32; idx += blockDim.x) {
        int f = idx >> 5, l = idx & 31;
        sRoot[f][l] = make_float2(root[f * 64 + 2 * l], root[f * 64 + 2 * l + 1]);
    }
    if (tid < 64) sCB[tid] = cbias[tid];

    int nFirst = blockIdx.x * 64;

    // ---- phase 1: per-node z accumulation from CSR-sorted (he, src), unroll 2, two halves ----
    for (int half = 0; half < 2; half++) {
        int gnode = half * 32 + (tid >> 3);
        int sub   = tid & 7;
        int n = nFirst + gnode;
        int j0 = 2 * sub;
        int o0 = 0, o1 = 0;
        if (n < N) {
            o0 = __ldg(&g_off[n]);
            o1 = __ldg(&g_off[n + 1]);
        }

        float zacc[16];
        #pragma unroll
        for (int i = 0; i < 16; i++) zacc[i] = 0.f;
        float xs[8];
        #pragma unroll
        for (int i = 0; i < 8; i++) xs[i] = 0.f;

        int i = o0;
        for (; i + 2 <= o1; i += 2) {
            float2 hA = __ldg((const float2*)(g_she + (size_t)i * 16 + j0));
            float2 hB = __ldg((const float2*)(g_she + (size_t)(i + 1) * 16 + j0));
            int sA = __ldg(&g_ssrc[i]);
            int sB = __ldg(&g_ssrc[i + 1]);
            const float4* xpA = (const float4*)(x + (size_t)sA * 8);
            const float4* xpB = (const float4*)(x + (size_t)sB * 8);
            float4 a0 = __ldg(xpA);
            float4 a1 = __ldg(xpA + 1);
            float4 b0 = __ldg(xpB);
            float4 b1 = __ldg(xpB + 1);

            zacc[0] = fmaf(hA.x, a0.x, zacc[0]);
            zacc[1] = fmaf(hA.x, a0.y, zacc[1]);
            zacc[2] = fmaf(hA.x, a0.z, zacc[2]);
            zacc[3] = fmaf(hA.x, a0.w, zacc[3]);
            zacc[4] = fmaf(hA.x, a1.x, zacc[4]);
            zacc[5] = fmaf(hA.x, a1.y, zacc[5]);
            zacc[6] = fmaf(hA.x, a1.z, zacc[6]);
            zacc[7] = fmaf(hA.x, a1.w, zacc[7]);
            zacc[8]  = fmaf(hA.y, a0.x, zacc[8]);
            zacc[9]  = fmaf(hA.y, a0.y, zacc[9]);
            zacc[10] = fmaf(hA.y, a0.z, zacc[10]);
            zacc[11] = fmaf(hA.y, a0.w, zacc[11]);
            zacc[12] = fmaf(hA.y, a1.x, zacc[12]);
            zacc[13] = fmaf(hA.y, a1.y, zacc[13]);
            zacc[14] = fmaf(hA.y, a1.z, zacc[14]);
            zacc[15] = fmaf(hA.y, a1.w, zacc[15]);

            zacc[0] = fmaf(hB.x, b0.x, zacc[0]);
            zacc[1] = fmaf(hB.x, b0.y, zacc[1]);
            zacc[2] = fmaf(hB.x, b0.z, zacc[2]);
            zacc[3] = fmaf(hB.x, b0.w, zacc[3]);
            zacc[4] = fmaf(hB.x, b1.x, zacc[4]);
            zacc[5] = fmaf(hB.x, b1.y, zacc[5]);
            zacc[6] = fmaf(hB.x, b1.z, zacc[6]);
            zacc[7] = fmaf(hB.x, b1.w, zacc[7]);
            zacc[8]  = fmaf(hB.y, b0.x, zacc[8]);
            zacc[9]  = fmaf(hB.y, b0.y, zacc[9]);
            zacc[10] = fmaf(hB.y, b0.z, zacc[10]);
            zacc[11] = fmaf(hB.y, b0.w, zacc[11]);
            zacc[12] = fmaf(hB.y, b1.x, zacc[12]);
            zacc[13] = fmaf(hB.y, b1.y, zacc[13]);
            zacc[14] = fmaf(hB.y, b1.z, zacc[14]);
            zacc[15] = fmaf(hB.y, b1.w, zacc[15]);

            if (sub == 0) {
                xs[0] += a0.x + b0.x; xs[1] += a0.y + b0.y;
                xs[2] += a0.z + b0.z; xs[3] += a0.w + b0.w;
                xs[4] += a1.x + b1.x; xs[5] += a1.y + b1.y;
                xs[6] += a1.z + b1.z; xs[7] += a1.w + b1.w;
            }
        }
        if (i < o1) {
            float2 h2 = __ldg((const float2*)(g_she + (size_t)i * 16 + j0));
            int src = __ldg(&g_ssrc[i]);
            const float4* xp = (const float4*)(x + (size_t)src * 8);
            float4 x0 = __ldg(xp);
            float4 x1 = __ldg(xp + 1);
            zacc[0] = fmaf(h2.x, x0.x, zacc[0]);
            zacc[1] = fmaf(h2.x, x0.y, zacc[1]);
            zacc[2] = fmaf(h2.x, x0.z, zacc[2]);
            zacc[3] = fmaf(h2.x, x0.w, zacc[3]);
            zacc[4] = fmaf(h2.x, x1.x, zacc[4]);
            zacc[5] = fmaf(h2.x, x1.y, zacc[5]);
            zacc[6] = fmaf(h2.x, x1.z, zacc[6]);
            zacc[7] = fmaf(h2.x, x1.w, zacc[7]);
            zacc[8]  = fmaf(h2.y, x0.x, zacc[8]);
            zacc[9]  = fmaf(h2.y, x0.y, zacc[9]);
            zacc[10] = fmaf(h2.y, x0.z, zacc[10]);
            zacc[11] = fmaf(h2.y, x0.w, zacc[11]);
            zacc[12] = fmaf(h2.y, x1.x, zacc[12]);
            zacc[13] = fmaf(h2.y, x1.y, zacc[13]);
            zacc[14] = fmaf(h2.y, x1.z, zacc[14]);
            zacc[15] = fmaf(h2.y, x1.w, zacc[15]);
            if (sub == 0) {
                xs[0] += x0.x; xs[1] += x0.y; xs[2] += x0.z; xs[3] += x0.w;
                xs[4] += x1.x; xs[5] += x1.y; xs[6] += x1.z; xs[7] += x1.w;
            }
        }

        float* zrow = sZ + gnode * ZDIM;
        #pragma unroll
        for (int f = 0; f < 8; f++) {
            zrow[j0 * 8 + f]       = zacc[f];
            zrow[(j0 + 1) * 8 + f] = zacc[8 + f];
        }
        if (sub == 0) {
            #pragma unroll
            for (int f = 0; f < 8; f++) zrow[128 + f] = xs[f];
            sInvDeg[gnode] = 1.f / fmaxf((float)(o1 - o0), 1.f);
        }
    }
    __syncthreads();

    // ---- phase 2: pre = (z @ Wc)*invdeg + x@root + bias (packed f32x2, 8 nodes/warp) ----
    int warp = tid >> 5, lane = tid & 31;
    int nlocbase = warp * 8;
    int nbase = nFirst + nlocbase;

    int  nn[8];
    bool valid[8];
    #pragma unroll
    for (int i = 0; i < 8; i++) {
        int nd = nbase + i;
        valid[i] = (nd < N);
        nn[i] = valid[i] ? nd : 0;
    }

    const float4* zr[8];
    #pragma unroll
    for (int i = 0; i < 8; i++)
        zr[i] = (const float4*)(sZ + (size_t)(nlocbase + i) * ZDIM);

    ull agg[8];
    #pragma unroll
    for (int i = 0; i < 8; i++) agg[i] = 0ull;

    for (int kk = 0; kk < ZDIM / 4; kk++) {
        ull wa = sWc[(4 * kk + 0) * 32 + lane];
        ull wb = sWc[(4 * kk + 1) * 32 + lane];
        ull wc = sWc[(4 * kk + 2) * 32 + lane];
        ull wd = sWc[(4 * kk + 3) * 32 + lane];
        #pragma unroll
        for (int i = 0; i < 8; i++) {
            float4 z = zr[i][kk];
            ull t;
            DUP2(t, z.x); FMA2(agg[i], t, wa);
            DUP2(t, z.y); FMA2(agg[i], t, wb);
            DUP2(t, z.z); FMA2(agg[i], t, wc);
            DUP2(t, z.w); FMA2(agg[i], t, wd);
        }
    }

    float2 ls = make_float2(0.f, 0.f), lq = make_float2(0.f, 0.f);
    #pragma unroll
    for (int i = 0; i < 8; i++) {
        float ax, ay;
        UNPACK2(ax, ay, agg[i]);
        float2 p = make_float2(sCB[2 * lane], sCB[2 * lane + 1]);
        const float* xr = x + (size_t)nn[i] * 8;
        #pragma unroll
        for (int f = 0; f < 8; f++) {
            float xv = __ldg(xr + f);
            float2 rw = sRoot[f][lane];
            p.x = fmaf(xv, rw.x, p.x);
            p.y = fmaf(xv, rw.y, p.y);
        }
        float invd = sInvDeg[nlocbase + i];
        p.x = fmaf(ax, invd, p.x);
        p.y = fmaf(ay, invd, p.y);
        if (valid[i]) {
            g_pre[(size_t)nn[i] * 64 + 2 * lane]     = p.x;
            g_pre[(size_t)nn[i] * 64 + 2 * lane + 1] = p.y;
            ls.x += p.x; ls.y += p.y;
            lq.x = fmaf(p.x, p.x, lq.x);
            lq.y = fmaf(p.y, p.y, lq.y);
        }
    }
    // all z reads done in this block before aliasing sZ as reduction space
    __syncthreads();
    redS[warp * 32 + lane] = ls;
    redQ[warp * 32 + lane] = lq;
    __syncthreads();
    if (tid < 32) {
        float2 S = make_float2(0.f, 0.f), Q = make_float2(0.f, 0.f);
        #pragma unroll
        for (int w = 0; w < 8; w++) {
            S.x += redS[w * 32 + tid].x; S.y += redS[w * 32 + tid].y;
            Q.x += redQ[w * 32 + tid].x; Q.y += redQ[w * 32 + tid].y;
        }
        atomicAdd(&g_colsum[2 * tid],     S.x);
        atomicAdd(&g_colsum[2 * tid + 1], S.y);
        atomicAdd(&g_colsq[2 * tid],      Q.x);
        atomicAdd(&g_colsq[2 * tid + 1],  Q.y);
    }
}

// ---------------- BN + relu + per-graph pool (one block per graph) ----------------
__global__ void k_pool(const float* __restrict__ gam,
                       const float* __restrict__ bet,
                       int N) {
    __shared__ float sScale[64], sShift[64];
    __shared__ float redS[8][64];
    __shared__ float redM[8][64];

    int tid = threadIdx.x;
    if (tid < 64) {
        float invN = 1.f / (float)N;
        float m = g_colsum[tid] * invN;
        float v = g_colsq[tid] * invN - m * m;
        float r = rsqrtf(v + EPS);
        float sc = r * __ldg(&gam[tid]);
        sScale[tid] = sc;
        sShift[tid] = __ldg(&bet[tid]) - m * sc;
    }
    __syncthreads();

    int rg = tid >> 6;
    int c  = tid & 63;
    int g = blockIdx.x;
    int s0 = g_start[g], s1 = g_start[g + 1];
    float sc = sScale[c], sh = sShift[c];

    float sum = 0.f, mx = 0.f;
    for (int n = s0 + rg; n < s1; n += 8) {
        float p = __ldg(&g_pre[(size_t)n * 64 + c]);
        float h = fmaxf(fmaf(p, sc, sh), 0.f);
        sum += h;
        mx = fmaxf(mx, h);
    }
    redS[rg][c] = sum;
    redM[rg][c] = mx;
    __syncthreads();
    if (tid < 64) {
        float S = 0.f, M = 0.f;
        #pragma unroll
        for (int r = 0; r < 8; r++) { S += redS[r][tid]; M = fmaxf(M, redM[r][tid]); }
        int cnt = s1 - s0;
        g_gfeat[g * 128 + tid]      = S / fmaxf((float)cnt, 1.f);
        g_gfeat[g * 128 + 64 + tid] = (cnt > 0) ? M : 0.f;
    }
}

// ---------------- fused linear + BN(over 64 rows) + relu ----------------
__global__ void k_layer(const float* __restrict__ in,   // [64, I]
                        const float* __restrict__ w,    // [I, O]
                        const float* __restrict__ b,
                        const float* __restrict__ gam,
                        const float* __restrict__ bet,
                        float* __restrict__ out,        // [64, O]
                        int I, int O) {
    extern __shared__ float sIn[];
    __shared__ float redS[8][32], redQ[8][32];
    __shared__ float sScale[32], sShift[32];

    int tid = threadIdx.x;
    for (int idx = tid; idx < 64 * I; idx += blockDim.x) sIn[idx] = in[idx];
    __syncthreads();

    int c = tid & 31, r0 = tid >> 5;
    int cg = blockIdx.x * 32 + c;

    float acc[8];
    float bv = __ldg(&b[cg]);
    #pragma unroll
    for (int i = 0; i < 8; i++) acc[i] = bv;

    for (int k = 0; k < I; k++) {
        float wv = __ldg(&w[k * O + cg]);
        #pragma unroll
        for (int i = 0; i < 8; i++)
            acc[i] = fmaf(sIn[(r0 + 8 * i) * I + k], wv, acc[i]);
    }

    float s = 0.f, q = 0.f;
    #pragma unroll
    for (int i = 0; i < 8; i++) { s += acc[i]; q = fmaf(acc[i], acc[i], q); }
    redS[r0][c] = s;
    redQ[r0][c] = q;
    __syncthreads();
    if (tid < 32) {
        float S = 0.f, Q = 0.f;
        #pragma unroll
        for (int w8 = 0; w8 < 8; w8++) { S += redS[w8][tid]; Q += redQ[w8][tid]; }
        float m = S * (1.f / 64.f);
        float v = Q * (1.f / 64.f) - m * m;
        float r = rsqrtf(v + EPS);
        float sc = r * __ldg(&gam[blockIdx.x * 32 + tid]);
        sScale[tid] = sc;
        sShift[tid] = __ldg(&bet[blockIdx.x * 32 + tid]) - m * sc;
    }
    __syncthreads();
    float sc = sScale[c], sh = sShift[c];
    #pragma unroll
    for (int i = 0; i < 8; i++)
        out[(r0 + 8 * i) * O + cg] = fmaxf(fmaf(acc[i], sc, sh), 0.f);
}

// ---------------- final projection [64,64]@[64,10] + scratch reset ----------------
__global__ void k_out(const float* __restrict__ wout,
                      const float* __restrict__ bout,
                      float* __restrict__ out) {
    int t = threadIdx.x;
    if (t < 64) { g_colsum[t] = 0.f; g_colsq[t] = 0.f; }   // reset for next replay
    if (t >= 640) return;
    int g = t / 10, o = t % 10;
    float s = __ldg(&bout[o]);
    #pragma unroll
    for (int k = 0; k < 64; k++)
        s = fmaf(g_y3[g * 64 + k], __ldg(&wout[k * 10 + o]), s);
    out[t] = s;
}

// ---------------- launch ----------------
extern "C" void kernel_launch(void* const* d_in, const int* in_sizes, int n_in,
                              void* d_out, int out_size) {
    const float* x      = (const float*)d_in[0];
    const int*   ei     = (const int*)  d_in[1];
    const float* ea     = (const float*)d_in[2];
    const int*   batch  = (const int*)  d_in[3];
    const float* w_e1   = (const float*)d_in[4];
    const float* b_e1   = (const float*)d_in[5];
    const float* w_e2   = (const float*)d_in[6];
    const float* b_e2   = (const float*)d_in[7];
    const float* root   = (const float*)d_in[8];
    const float* cbias  = (const float*)d_in[9];
    const float* g_bnc  = (const float*)d_in[10];
    const float* b_bnc  = (const float*)d_in[11];
    const float* w1     = (const float*)d_in[12];
    const float* b1     = (const float*)d_in[13];
    const float* g1     = (const float*)d_in[14];
    const float* be1    = (const float*)d_in[15];
    const float* w2     = (const float*)d_in[16];
    const float* b2     = (const float*)d_in[17];
    const float* g2     = (const float*)d_in[18];
    const float* be2    = (const float*)d_in[19];
    const float* w3     = (const float*)d_in[20];
    const float* b3     = (const float*)d_in[21];
    const float* g3     = (const float*)d_in[22];
    const float* be3    = (const float*)d_in[23];
    const float* wout   = (const float*)d_in[24];
    const float* bout   = (const float*)d_in[25];

    int N = in_sizes[0] / 8;
    int E = in_sizes[2] / 8;
    if (N > NMAX) N = NMAX;
    if (E > EMAX) E = EMAX;

    void *p_gfeat, *p_y1, *p_y2, *p_y3;
    cudaGetSymbolAddress(&p_gfeat, g_gfeat);
    cudaGetSymbolAddress(&p_y1, g_y1);
    cudaGetSymbolAddress(&p_y2, g_y2);
    cudaGetSymbolAddress(&p_y3, g_y3);

    const int fusedSmem = ZDIM * 32 * 8 + 64 * ZDIM * 4;   // sWc + sZ = 69632 B
    cudaFuncSetAttribute(k_fused, cudaFuncAttributeMaxDynamicSharedMemorySize, fusedSmem);
    cudaFuncSetAttribute(k_layer, cudaFuncAttributeMaxDynamicSharedMemorySize,
                         64 * 256 * (int)sizeof(float));

    int cover = (E > N ? E : N);
    k_hist<<<(cover + 255) / 256, 256>>>(ei, batch, N, E);
    k_scan<<<SCAN_B, SCAN_T>>>(N, E);
    k_scatter<<<(E + 255) / 256, 256>>>(ei, ea, w_e1, b_e1, E);
    k_fused<<<(N + 63) / 64, 256, fusedSmem>>>(x, w_e2, b_e2, root, cbias, N);
    k_pool<<<GRAPHS, 512>>>(g_bnc, b_bnc, N);
    k_layer<<<8, 256, 64 * 128 * sizeof(float)>>>((const float*)p_gfeat, w1, b1, g1, be1, (float*)p_y1, 128, 256);
    k_layer<<<4, 256, 64 * 256 * sizeof(float)>>>((const float*)p_y1,    w2, b2, g2, be2, (float*)p_y2, 256, 128);
    k_layer<<<2, 256, 64 * 128 * sizeof(float)>>>((const float*)p_y2,    w3, b3, g3, be3, (float*)p_y3, 128, 64);
    k_out<<<1, 640>>>(wout, bout, (float*)d_out);
}